// round 5
// baseline (speedup 1.0000x reference)
#include <cuda_runtime.h>
#include <cuda_bf16.h>
#include <cuda_fp16.h>
#include <cstdint>
#include <cstring>

// NT-Xent contrastive loss, sm_103 baseline ISA, int8 tensor-core path.
//   q = round(127 * normalize(z))  (s8, exact int32 dot via mma.m16n8k32.s8)
//   S_i = sum_j exp2(SC * dot_q(i,j)),  SC = 2*log2(e)/127^2
//   loss = mean( log(S_i - diag_i) - pos_i );  diag exact, pos fp32 from raw z.

#define N2    8192
#define NHALF 4096
#define DD    128
#define NTILE 32
#define RSTRIDE 144                 // 128B row + 16B pad: conflict-free ldmatrix
#define TILE_SM (128 * RSTRIDE)     // 18432 B

__device__ __align__(16) uint32_t g_q[(size_t)N2 * 32];   // s8 rows, 128B each
__device__ float g_S[2 * N2];
__device__ float g_pos[N2];
__device__ float g_diag[N2];

// ---------------- PTX helpers ----------------
__device__ __forceinline__ uint32_t smem_u32(const void* p) {
    uint32_t a;
    asm("{ .reg .u64 t; cvta.to.shared.u64 t, %1; cvt.u32.u64 %0, t; }" : "=r"(a) : "l"(p));
    return a;
}
__device__ __forceinline__ void cp16(uint32_t dst, const void* src) {
    asm volatile("cp.async.cg.shared.global [%0], [%1], 16;" :: "r"(dst), "l"(src));
}
#define CP_COMMIT() asm volatile("cp.async.commit_group;" ::: "memory")
#define CP_WAIT1()  asm volatile("cp.async.wait_group 1;" ::: "memory")

#define LDSM4(r0, r1, r2, r3, addr)                                              \
    asm volatile("ldmatrix.sync.aligned.m8n8.x4.shared.b16 {%0,%1,%2,%3}, [%4];" \
                 : "=r"(r0), "=r"(r1), "=r"(r2), "=r"(r3) : "r"(addr))

#define IMMA16832(c, a, b0, b1)                                                \
    asm volatile("mma.sync.aligned.m16n8k32.row.col.s32.s8.s8.s32 "            \
                 "{%0,%1,%2,%3}, {%4,%5,%6,%7}, {%8,%9}, {%0,%1,%2,%3};"       \
                 : "+r"((c)[0]), "+r"((c)[1]), "+r"((c)[2]), "+r"((c)[3])      \
                 : "r"((a)[0]), "r"((a)[1]), "r"((a)[2]), "r"((a)[3]),         \
                   "r"(b0), "r"(b1))

__device__ __forceinline__ float fast_lg2(float x) {
    float y; asm("lg2.approx.f32 %0, %1;" : "=f"(y) : "f"(x)); return y;
}

// SC = (2*log2 e) / 127^2 : maps int dot -> exp2 argument
#define SCALE_LOG2 (2.8853900817779268f / 16129.0f)

// ---------------- 1) prep: normalize -> s8 quant, diag, pos ----------------
__global__ void prep_kernel(const float* __restrict__ zi, const float* __restrict__ zj) {
    int w    = (blockIdx.x * blockDim.x + threadIdx.x) >> 5;
    int lane = threadIdx.x & 31;
    if (w >= NHALF) return;
    float4 a = reinterpret_cast<const float4*>(zi + (size_t)w * DD)[lane];
    float4 b = reinterpret_cast<const float4*>(zj + (size_t)w * DD)[lane];
    float sa = a.x * a.x + a.y * a.y + a.z * a.z + a.w * a.w;
    float sb = b.x * b.x + b.y * b.y + b.z * b.z + b.w * b.w;
    float dp = a.x * b.x + a.y * b.y + a.z * b.z + a.w * b.w;
#pragma unroll
    for (int o = 16; o > 0; o >>= 1) {
        sa += __shfl_xor_sync(0xffffffffu, sa, o);
        sb += __shfl_xor_sync(0xffffffffu, sb, o);
        dp += __shfl_xor_sync(0xffffffffu, dp, o);
    }
    float ia = rsqrtf(sa) * 127.0f, ib = rsqrtf(sb) * 127.0f;

    int qa0 = __float2int_rn(a.x * ia), qa1 = __float2int_rn(a.y * ia);
    int qa2 = __float2int_rn(a.z * ia), qa3 = __float2int_rn(a.w * ia);
    int qb0 = __float2int_rn(b.x * ib), qb1 = __float2int_rn(b.y * ib);
    int qb2 = __float2int_rn(b.z * ib), qb3 = __float2int_rn(b.w * ib);

    int sqa = qa0*qa0 + qa1*qa1 + qa2*qa2 + qa3*qa3;
    int sqb = qb0*qb0 + qb1*qb1 + qb2*qb2 + qb3*qb3;
#pragma unroll
    for (int o = 16; o > 0; o >>= 1) {
        sqa += __shfl_xor_sync(0xffffffffu, sqa, o);
        sqb += __shfl_xor_sync(0xffffffffu, sqb, o);
    }
    if (lane == 0) {
        float p = 2.0f * dp * rsqrtf(sa) * rsqrtf(sb);
        g_pos[w] = p; g_pos[w + NHALF] = p;
        g_diag[w]         = exp2f(SCALE_LOG2 * (float)sqa);
        g_diag[w + NHALF] = exp2f(SCALE_LOG2 * (float)sqb);
    }
    uint32_t ua = (uint32_t)(qa0 & 0xff) | ((uint32_t)(qa1 & 0xff) << 8) |
                  ((uint32_t)(qa2 & 0xff) << 16) | ((uint32_t)qa3 << 24);
    uint32_t ub = (uint32_t)(qb0 & 0xff) | ((uint32_t)(qb1 & 0xff) << 8) |
                  ((uint32_t)(qb2 & 0xff) << 16) | ((uint32_t)qb3 << 24);
    g_q[(size_t)w * 32 + lane] = ua;
    g_q[(size_t)(w + NHALF) * 32 + lane] = ub;
}

// ---------------- 2) fused IMMA GEMM + exp2/rowsum ----------------
// grid=128: band=bx>>1 (128 rows), split=bx&1 (4096 cols).
// 8 warps = wm(0..1, 64 rows) x wn(0..3, 32 cols). A fragments register-resident.
__device__ __forceinline__ void load_tile(uint32_t dstBase, const uint32_t* src,
                                          int tid) {
#pragma unroll
    for (int p = 0; p < 4; ++p) {
        int id = p * 256 + tid;          // 0..1023 chunks of 16B
        int row = id >> 3, ch = id & 7;
        cp16(dstBase + row * RSTRIDE + ch * 16,
             reinterpret_cast<const char*>(src) + row * 128 + ch * 16);
    }
}

__global__ __launch_bounds__(256, 1) void simlse_kernel() {
    extern __shared__ unsigned char smem[];
    const uint32_t sb   = smem_u32(smem);
    const uint32_t smA  = sb;
    const uint32_t smB0 = sb + TILE_SM;

    const int tid  = threadIdx.x, wid = tid >> 5, lane = tid & 31;
    const int band = blockIdx.x >> 1, split = blockIdx.x & 1;
    const int r0   = band * 128;
    const int wn   = wid & 3;          // 4 col groups (32 cols)
    const int wm   = wid >> 2;         // 2 row groups (64 rows)

    // per-lane ldmatrix offset: matrices (rows0-7,klo),(rows8-15,klo),(rows0-7,khi),(rows8-15,khi)
    const uint32_t mOff =
        (uint32_t)(((lane >> 3) & 1) * 8 + (lane & 7)) * RSTRIDE +
        (uint32_t)(((lane >> 4) & 1) * 16);

    const uint32_t* gB = g_q + (size_t)split * 4096 * 32;

    load_tile(smA,  g_q + (size_t)r0 * 32, tid);
    load_tile(smB0, gB, tid);
    CP_COMMIT();
    load_tile(smB0 + TILE_SM, gB + (size_t)128 * 32, tid);
    CP_COMMIT();
    CP_WAIT1();
    __syncthreads();

    // A fragments resident: 64 rows x 128 k = 64 regs
    uint32_t afr[4][4][4];
    {
        const uint32_t aBase = smA + (uint32_t)(wm * 64) * RSTRIDE + mOff;
#pragma unroll
        for (int mb = 0; mb < 4; ++mb)
#pragma unroll
            for (int ks = 0; ks < 4; ++ks)
                LDSM4(afr[mb][ks][0], afr[mb][ks][1], afr[mb][ks][2], afr[mb][ks][3],
                      aBase + (uint32_t)(mb * 16) * RSTRIDE + (uint32_t)(ks * 32));
    }

    const __half2 zero2 = __float2half2_rn(0.f);
    float frow[4][2] = {{0.f,0.f},{0.f,0.f},{0.f,0.f},{0.f,0.f}};
    const float SC = SCALE_LOG2;

    for (int it = 0; it < NTILE; ++it) {
        __half2 sum01[4] = {zero2, zero2, zero2, zero2};
        __half2 sum23[4] = {zero2, zero2, zero2, zero2};
#pragma unroll
        for (int np = 0; np < 2; ++np) {
            const uint32_t bBase = smB0 + (uint32_t)(it & 1) * TILE_SM +
                                   (uint32_t)(wn * 32 + np * 16) * RSTRIDE + mOff;
            uint32_t bfr[4][4];
#pragma unroll
            for (int ks = 0; ks < 4; ++ks)
                LDSM4(bfr[ks][0], bfr[ks][1], bfr[ks][2], bfr[ks][3],
                      bBase + (uint32_t)(ks * 32));

            int acc[4][2][4];
#pragma unroll
            for (int mb = 0; mb < 4; ++mb)
#pragma unroll
                for (int nb = 0; nb < 2; ++nb)
#pragma unroll
                    for (int r = 0; r < 4; ++r) acc[mb][nb][r] = 0;

#pragma unroll
            for (int ks = 0; ks < 4; ++ks)
#pragma unroll
                for (int mb = 0; mb < 4; ++mb) {
                    IMMA16832(acc[mb][0], afr[mb][ks], bfr[ks][0], bfr[ks][2]);
                    IMMA16832(acc[mb][1], afr[mb][ks], bfr[ks][1], bfr[ks][3]);
                }

#pragma unroll
            for (int mb = 0; mb < 4; ++mb)
#pragma unroll
                for (int nb = 0; nb < 2; ++nb) {
                    __half2 e01 = h2exp2(__floats2half2_rn((float)acc[mb][nb][0] * SC,
                                                           (float)acc[mb][nb][1] * SC));
                    __half2 e23 = h2exp2(__floats2half2_rn((float)acc[mb][nb][2] * SC,
                                                           (float)acc[mb][nb][3] * SC));
                    sum01[mb] = __hadd2(sum01[mb], e01);
                    sum23[mb] = __hadd2(sum23[mb], e23);
                }
        }
        // flush to fp32 (per-iter lane sums <= ~60: fp16-safe)
#pragma unroll
        for (int mb = 0; mb < 4; ++mb) {
            float2 f0 = __half22float2(sum01[mb]);
            float2 f1 = __half22float2(sum23[mb]);
            frow[mb][0] += f0.x + f0.y;
            frow[mb][1] += f1.x + f1.y;
        }

        __syncthreads();
        if (it + 2 < NTILE)
            load_tile(smB0 + (uint32_t)(it & 1) * TILE_SM,
                      gB + (size_t)(it + 2) * 128 * 32, tid);
        CP_COMMIT();
        if (it + 1 < NTILE) { CP_WAIT1(); __syncthreads(); }
    }

    // quad reduction: lanes within a quad share rows, differ in cols
#pragma unroll
    for (int mb = 0; mb < 4; ++mb)
#pragma unroll
        for (int h = 0; h < 2; ++h) {
            frow[mb][h] += __shfl_xor_sync(0xffffffffu, frow[mb][h], 1);
            frow[mb][h] += __shfl_xor_sync(0xffffffffu, frow[mb][h], 2);
        }

    __syncthreads();
    float* part = reinterpret_cast<float*>(smem);   // [4 wn][128 rows]
    if ((lane & 3) == 0) {
        int q = lane >> 2;
#pragma unroll
        for (int mb = 0; mb < 4; ++mb) {
            part[wn * 128 + wm * 64 + mb * 16 + q + 0] = frow[mb][0];
            part[wn * 128 + wm * 64 + mb * 16 + q + 8] = frow[mb][1];
        }
    }
    __syncthreads();
    if (tid < 128)
        g_S[split * N2 + r0 + tid] =
            part[tid] + part[128 + tid] + part[256 + tid] + part[384 + tid];
}

// ---------------- 3) finish ----------------
__global__ void finish_kernel(float* __restrict__ out) {
    __shared__ float red[32];
    const int t = threadIdx.x, lane = t & 31, w = t >> 5;
    const float LN2 = 0.6931471805599453f;
    float s = 0.f;
#pragma unroll
    for (int u = 0; u < 2; ++u) {
        int i = t * 8 + u * 4;
        float4 s0 = *reinterpret_cast<const float4*>(g_S + i);
        float4 s1 = *reinterpret_cast<const float4*>(g_S + N2 + i);
        float4 dg = *reinterpret_cast<const float4*>(g_diag + i);
        float4 pp = *reinterpret_cast<const float4*>(g_pos + i);
        s += (fast_lg2(s0.x + s1.x - dg.x) * LN2 - pp.x);
        s += (fast_lg2(s0.y + s1.y - dg.y) * LN2 - pp.y);
        s += (fast_lg2(s0.z + s1.z - dg.z) * LN2 - pp.z);
        s += (fast_lg2(s0.w + s1.w - dg.w) * LN2 - pp.w);
    }
#pragma unroll
    for (int o = 16; o > 0; o >>= 1) s += __shfl_xor_sync(0xffffffffu, s, o);
    if (lane == 0) red[w] = s;
    __syncthreads();
    if (w == 0) {
        float v = red[lane];
#pragma unroll
        for (int o = 16; o > 0; o >>= 1) v += __shfl_xor_sync(0xffffffffu, v, o);
        if (lane == 0) out[0] = v * (1.0f / (float)N2);
    }
}

// ---------------- launch ----------------
extern "C" void kernel_launch(void* const* d_in, const int* in_sizes, int n_in,
                              void* d_out, int out_size) {
    const float* zi = (const float*)d_in[0];
    const float* zj = (const float*)d_in[1];
    cudaFuncSetAttribute(simlse_kernel, cudaFuncAttributeMaxDynamicSharedMemorySize,
                         3 * TILE_SM);
    prep_kernel<<<NHALF / 8, 256>>>(zi, zj);
    simlse_kernel<<<128, 256, 3 * TILE_SM>>>();
    finish_kernel<<<1, 1024>>>((float*)d_out);
}

// round 6
// speedup vs baseline: 3.4079x; 3.4079x over previous
#include <cuda_runtime.h>
#include <cuda_bf16.h>
#include <cuda_fp16.h>
#include <cstdint>
#include <cstring>

// NT-Xent contrastive loss, sm_103 baseline ISA (mma.sync bf16 + ldmatrix + cp.async).
// SYMMETRY: sim is symmetric -> compute only upper-triangle 128x128 tiles (I<=J).
// Off-diag tile (I,J): exp-row-sums -> band I, exp-col-sums -> band J.
// Accumulation into g_S as u64 fixed point (x 2^36) via atomicAdd: deterministic.
//   g_znA = normalize(z) * 2*log2(e) (bf16), g_znB = normalize(z) (bf16)
//   loss = mean( ln(S_i - diag_i) - pos_i ), diag exact from bf16, pos fp32.

#define N2    8192
#define DD    128
#define NHALF 4096
#define RSTRIDE 272
#define TILE_SM (128 * RSTRIDE)          // 34816
#define SM_COLRED (3 * TILE_SM)          // 2*128 floats
#define SM_ROWRED (3 * TILE_SM + 1024)   // 4*128 floats
#define SMEM_TOTAL (3 * TILE_SM + 3072)
#define FXSCALE 68719476736.0f           // 2^36

__device__ __align__(16) __nv_bfloat16 g_znA[(size_t)N2 * DD];
__device__ __align__(16) __nv_bfloat16 g_znB[(size_t)N2 * DD];
__device__ unsigned long long g_S[N2];
__device__ float g_pos[N2];
__device__ float g_diag[N2];

// ---------------- PTX helpers ----------------
__device__ __forceinline__ uint32_t smem_u32(const void* p) {
    uint32_t a;
    asm("{ .reg .u64 t; cvta.to.shared.u64 t, %1; cvt.u32.u64 %0, t; }" : "=r"(a) : "l"(p));
    return a;
}
__device__ __forceinline__ void cp16(uint32_t dst, const void* src) {
    asm volatile("cp.async.cg.shared.global [%0], [%1], 16;" :: "r"(dst), "l"(src));
}
#define CP_COMMIT() asm volatile("cp.async.commit_group;" ::: "memory")
#define CP_WAIT1()  asm volatile("cp.async.wait_group 1;" ::: "memory")
#define CP_WAIT0()  asm volatile("cp.async.wait_group 0;" ::: "memory")

#define LDSM4(r0, r1, r2, r3, addr)                                              \
    asm volatile("ldmatrix.sync.aligned.m8n8.x4.shared.b16 {%0,%1,%2,%3}, [%4];" \
                 : "=r"(r0), "=r"(r1), "=r"(r2), "=r"(r3) : "r"(addr))

#define MMA16816(c, a, b0, b1)                                                 \
    asm volatile("mma.sync.aligned.m16n8k16.row.col.f32.bf16.bf16.f32 "        \
                 "{%0,%1,%2,%3}, {%4,%5,%6,%7}, {%8,%9}, {%0,%1,%2,%3};"       \
                 : "+f"((c)[0]), "+f"((c)[1]), "+f"((c)[2]), "+f"((c)[3])      \
                 : "r"((a)[0]), "r"((a)[1]), "r"((a)[2]), "r"((a)[3]),         \
                   "r"(b0), "r"(b1))

__device__ __forceinline__ float fast_lg2(float x) {
    float y; asm("lg2.approx.f32 %0, %1;" : "=f"(y) : "f"(x)); return y;
}

// ---------------- 1) prep ----------------
__global__ void prep_kernel(const float* __restrict__ zi, const float* __restrict__ zj) {
    int gtid = blockIdx.x * blockDim.x + threadIdx.x;
    if (gtid < N2) g_S[gtid] = 0ull;     // zero accumulators (runs before simlse)
    int w    = gtid >> 5;
    int lane = threadIdx.x & 31;
    if (w >= NHALF) return;
    float4 a = reinterpret_cast<const float4*>(zi + (size_t)w * DD)[lane];
    float4 b = reinterpret_cast<const float4*>(zj + (size_t)w * DD)[lane];
    float sa = a.x * a.x + a.y * a.y + a.z * a.z + a.w * a.w;
    float sb = b.x * b.x + b.y * b.y + b.z * b.z + b.w * b.w;
    float dp = a.x * b.x + a.y * b.y + a.z * b.z + a.w * b.w;
#pragma unroll
    for (int o = 16; o > 0; o >>= 1) {
        sa += __shfl_xor_sync(0xffffffffu, sa, o);
        sb += __shfl_xor_sync(0xffffffffu, sb, o);
        dp += __shfl_xor_sync(0xffffffffu, dp, o);
    }
    float ia = rsqrtf(sa), ib = rsqrtf(sb);
    const float CA = 2.8853900817779268f;   // 2 * log2(e)
    float iaC = ia * CA, ibC = ib * CA;

    __nv_bfloat16 sA[4], pA[4], sB[4], pB[4];
    sA[0]=__float2bfloat16_rn(a.x*iaC); sA[1]=__float2bfloat16_rn(a.y*iaC);
    sA[2]=__float2bfloat16_rn(a.z*iaC); sA[3]=__float2bfloat16_rn(a.w*iaC);
    pA[0]=__float2bfloat16_rn(a.x*ia);  pA[1]=__float2bfloat16_rn(a.y*ia);
    pA[2]=__float2bfloat16_rn(a.z*ia);  pA[3]=__float2bfloat16_rn(a.w*ia);
    sB[0]=__float2bfloat16_rn(b.x*ibC); sB[1]=__float2bfloat16_rn(b.y*ibC);
    sB[2]=__float2bfloat16_rn(b.z*ibC); sB[3]=__float2bfloat16_rn(b.w*ibC);
    pB[0]=__float2bfloat16_rn(b.x*ib);  pB[1]=__float2bfloat16_rn(b.y*ib);
    pB[2]=__float2bfloat16_rn(b.z*ib);  pB[3]=__float2bfloat16_rn(b.w*ib);

    // exact self-dot of the quantized values (matches what the MMA computes)
    float da = 0.f, db = 0.f;
#pragma unroll
    for (int k = 0; k < 4; ++k) {
        da += __bfloat162float(sA[k]) * __bfloat162float(pA[k]);
        db += __bfloat162float(sB[k]) * __bfloat162float(pB[k]);
    }
#pragma unroll
    for (int o = 16; o > 0; o >>= 1) {
        da += __shfl_xor_sync(0xffffffffu, da, o);
        db += __shfl_xor_sync(0xffffffffu, db, o);
    }
    if (lane == 0) {
        float p = 2.0f * dp * ia * ib;
        g_pos[w] = p; g_pos[w + NHALF] = p;
        g_diag[w]         = exp2f(da);
        g_diag[w + NHALF] = exp2f(db);
    }
    uint2 u;
    memcpy(&u, sA, 8);
    reinterpret_cast<uint2*>(g_znA + (size_t)w * DD)[lane] = u;
    memcpy(&u, pA, 8);
    reinterpret_cast<uint2*>(g_znB + (size_t)w * DD)[lane] = u;
    memcpy(&u, sB, 8);
    reinterpret_cast<uint2*>(g_znA + (size_t)(w + NHALF) * DD)[lane] = u;
    memcpy(&u, pB, 8);
    reinterpret_cast<uint2*>(g_znB + (size_t)(w + NHALF) * DD)[lane] = u;
}

// ---------------- 2) fused symmetric HMMA + exp2 row/col sums ----------------
__device__ __forceinline__ void load_tile(uint32_t dstBase, const __nv_bfloat16* src,
                                          int tid) {
#pragma unroll
    for (int p = 0; p < 8; ++p) {
        int id = p * 256 + tid;
        int row = id >> 4, ch = id & 15;
        cp16(dstBase + row * RSTRIDE + ch * 16,
             reinterpret_cast<const char*>(src) + row * 256 + ch * 16);
    }
}

__global__ __launch_bounds__(256, 1) void simlse_kernel() {
    extern __shared__ unsigned char smem[];
    const uint32_t sb   = smem_u32(smem);
    const uint32_t smA  = sb;
    const uint32_t smB0 = sb + TILE_SM;
    float* colred = reinterpret_cast<float*>(smem + SM_COLRED);   // [2][128]
    float* rowred = reinterpret_cast<float*>(smem + SM_ROWRED);   // [4][128]

    const int tid = threadIdx.x, wid = tid >> 5, lane = tid & 31;
    const int bi    = blockIdx.x >> 2;     // 0..31
    const int chunk = blockIdx.x & 3;      // 0..3
    const int wn = wid & 3, wm = wid >> 2;

    const uint32_t aOff = (uint32_t)(lane & 15) * RSTRIDE + (uint32_t)((lane >> 4) << 4);
    const uint32_t bOff = (uint32_t)((lane & 7) + ((lane & 16) ? 8 : 0)) * RSTRIDE +
                          (uint32_t)((lane & 8) ? 16 : 0);
    const __half2 zero2 = __float2half2_rn(0.f);

#pragma unroll 1
    for (int phase = 0; phase < 2; ++phase) {
        const int I = phase ? (63 - bi) : bi;
        const int nJ = (63 - I - chunk) / 4 + ((I + chunk <= 63) ? 1 : 0);
        if (nJ <= 0) continue;

        // ---- load A band I, make fragments resident ----
        load_tile(smA, g_znA + (size_t)I * 128 * DD, tid);
        CP_COMMIT();
        CP_WAIT0();
        __syncthreads();
        uint32_t afr[4][8][4];
        {
            const uint32_t aBase = smA + (uint32_t)(wm * 64) * RSTRIDE + aOff;
#pragma unroll
            for (int mb = 0; mb < 4; ++mb)
#pragma unroll
                for (int ks = 0; ks < 8; ++ks)
                    LDSM4(afr[mb][ks][0], afr[mb][ks][1], afr[mb][ks][2], afr[mb][ks][3],
                          aBase + (uint32_t)(mb * 16) * RSTRIDE + (uint32_t)(ks * 32));
        }

        // ---- B pipeline prologue ----
        load_tile(smB0, g_znB + (size_t)(I + chunk) * 128 * DD, tid);
        CP_COMMIT();
        if (nJ > 1)
            load_tile(smB0 + TILE_SM, g_znB + (size_t)(I + chunk + 4) * 128 * DD, tid);
        CP_COMMIT();

        float frow[4][2] = {{0.f,0.f},{0.f,0.f},{0.f,0.f},{0.f,0.f}};

#pragma unroll 1
        for (int t = 0; t < nJ; ++t) {
            const int J = I + chunk + 4 * t;
            const int s = t & 1;
            CP_WAIT1();
            __syncthreads();

            __half2 cs[2][2] = {{zero2, zero2}, {zero2, zero2}};
            __half2 sum01[4] = {zero2, zero2, zero2, zero2};
            __half2 sum23[4] = {zero2, zero2, zero2, zero2};
#pragma unroll
            for (int np = 0; np < 2; ++np) {
                const uint32_t bBase = smB0 + (uint32_t)s * TILE_SM +
                                       (uint32_t)(wn * 32 + np * 16) * RSTRIDE + bOff;
                uint32_t bfr[8][4];
#pragma unroll
                for (int ks = 0; ks < 8; ++ks)
                    LDSM4(bfr[ks][0], bfr[ks][1], bfr[ks][2], bfr[ks][3],
                          bBase + (uint32_t)(ks * 32));

                float acc[4][2][4];
#pragma unroll
                for (int mb = 0; mb < 4; ++mb)
#pragma unroll
                    for (int nb = 0; nb < 2; ++nb)
#pragma unroll
                        for (int r = 0; r < 4; ++r) acc[mb][nb][r] = 0.f;
#pragma unroll
                for (int ks = 0; ks < 8; ++ks)
#pragma unroll
                    for (int mb = 0; mb < 4; ++mb) {
                        MMA16816(acc[mb][0], afr[mb][ks], bfr[ks][0], bfr[ks][1]);
                        MMA16816(acc[mb][1], afr[mb][ks], bfr[ks][2], bfr[ks][3]);
                    }
#pragma unroll
                for (int mb = 0; mb < 4; ++mb)
#pragma unroll
                    for (int nb = 0; nb < 2; ++nb) {
                        __half2 e01 = h2exp2(__floats2half2_rn(acc[mb][nb][0], acc[mb][nb][1]));
                        __half2 e23 = h2exp2(__floats2half2_rn(acc[mb][nb][2], acc[mb][nb][3]));
                        sum01[mb] = __hadd2(sum01[mb], e01);
                        sum23[mb] = __hadd2(sum23[mb], e23);
                        cs[np][nb] = __hadd2(cs[np][nb], __hadd2(e01, e23));
                    }
            }
            // rows -> fp32 accumulators
#pragma unroll
            for (int mb = 0; mb < 4; ++mb) {
                float2 f0 = __half22float2(sum01[mb]);
                float2 f1 = __half22float2(sum23[mb]);
                frow[mb][0] += f0.x + f0.y;
                frow[mb][1] += f1.x + f1.y;
            }
            // cols: reduce over lane groups (xor 4,8,16), lanes 0..3 publish
#pragma unroll
            for (int np = 0; np < 2; ++np)
#pragma unroll
                for (int nb = 0; nb < 2; ++nb) {
                    __half2 v = cs[np][nb];
                    v = __hadd2(v, __shfl_xor_sync(0xffffffffu, v, 4));
                    v = __hadd2(v, __shfl_xor_sync(0xffffffffu, v, 8));
                    v = __hadd2(v, __shfl_xor_sync(0xffffffffu, v, 16));
                    if (lane < 4) {
                        float2 f = __half22float2(v);
                        int c = wn * 32 + np * 16 + nb * 8 + lane * 2;
                        colred[wm * 128 + c + 0] = f.x;
                        colred[wm * 128 + c + 1] = f.y;
                    }
                }
            __syncthreads();   // colred ready; all reads of stage s done
            if (J != I && tid < 128) {
                float v = colred[tid] + colred[128 + tid];
                atomicAdd(&g_S[J * 128 + tid], __float2ull_rn(v * FXSCALE));
            }
            if (t + 2 < nJ)
                load_tile(smB0 + (uint32_t)s * TILE_SM,
                          g_znB + (size_t)(J + 8) * 128 * DD, tid);
            CP_COMMIT();
        }

        // ---- flush row sums for band I ----
#pragma unroll
        for (int mb = 0; mb < 4; ++mb)
#pragma unroll
            for (int h = 0; h < 2; ++h) {
                frow[mb][h] += __shfl_xor_sync(0xffffffffu, frow[mb][h], 1);
                frow[mb][h] += __shfl_xor_sync(0xffffffffu, frow[mb][h], 2);
            }
        __syncthreads();
        if ((lane & 3) == 0) {
            int q = lane >> 2;
#pragma unroll
            for (int mb = 0; mb < 4; ++mb) {
                rowred[wn * 128 + wm * 64 + mb * 16 + q + 0] = frow[mb][0];
                rowred[wn * 128 + wm * 64 + mb * 16 + q + 8] = frow[mb][1];
            }
        }
        __syncthreads();
        if (tid < 128) {
            float v = rowred[tid] + rowred[128 + tid] + rowred[256 + tid] + rowred[384 + tid];
            atomicAdd(&g_S[I * 128 + tid], __float2ull_rn(v * FXSCALE));
        }
        __syncthreads();
    }
}

// ---------------- 3) finish ----------------
__global__ void finish_kernel(float* __restrict__ out) {
    __shared__ float red[32];
    const int t = threadIdx.x, lane = t & 31, w = t >> 5;
    const float LN2 = 0.6931471805599453f;
    const float INV = 1.0f / FXSCALE;
    float s = 0.f;
#pragma unroll
    for (int u = 0; u < 8; ++u) {
        int i = t + u * 1024;
        float S = __ull2float_rn(g_S[i]) * INV;
        s += fast_lg2(S - g_diag[i]) * LN2 - g_pos[i];
    }
#pragma unroll
    for (int o = 16; o > 0; o >>= 1) s += __shfl_xor_sync(0xffffffffu, s, o);
    if (lane == 0) red[w] = s;
    __syncthreads();
    if (w == 0) {
        float v = red[lane];
#pragma unroll
        for (int o = 16; o > 0; o >>= 1) v += __shfl_xor_sync(0xffffffffu, v, o);
        if (lane == 0) out[0] = v * (1.0f / (float)N2);
    }
}

// ---------------- launch ----------------
extern "C" void kernel_launch(void* const* d_in, const int* in_sizes, int n_in,
                              void* d_out, int out_size) {
    const float* zi = (const float*)d_in[0];
    const float* zj = (const float*)d_in[1];
    cudaFuncSetAttribute(simlse_kernel, cudaFuncAttributeMaxDynamicSharedMemorySize,
                         SMEM_TOTAL);
    prep_kernel<<<NHALF / 8, 256>>>(zi, zj);
    simlse_kernel<<<128, 256, SMEM_TOTAL>>>();
    finish_kernel<<<1, 1024>>>((float*)d_out);
}